// round 1
// baseline (speedup 1.0000x reference)
#include <cuda_runtime.h>
#include <math.h>

#define MROWS 8192            // B*T
#define KDIM  2048            // I
#define NDIM  2048            // C
#define TLEN  4096            // T

// Scratch for H = tanh(relu(rope(X@W)) + b)   (64 MiB, static device global)
__device__ float g_H[(size_t)MROWS * NDIM];

// ---------------------------------------------------------------------------
// Kernel 1: fused GEMM + RoPE + ReLU + bias + tanh  ->  g_H  (row-major M x N)
// CTA tile 128x128, BK=16, 256 threads, each thread 8x8 split as 2x2 of 4x4.
// ---------------------------------------------------------------------------
__global__ __launch_bounds__(256, 2)
void gemm_fused(const float* __restrict__ X, const float* __restrict__ W,
                const float* __restrict__ hh_b)
{
    __shared__ float Xs[2][16][128];   // [buf][k][m]
    __shared__ float Ws[2][16][128];   // [buf][k][n]

    const int tid = threadIdx.x;
    const int tx  = tid & 15;          // n direction (16)
    const int ty  = tid >> 4;          // m direction (16)
    const int m0  = blockIdx.y * 128;
    const int n0  = blockIdx.x * 128;

    float acc[8][8];
#pragma unroll
    for (int i = 0; i < 8; ++i)
#pragma unroll
        for (int j = 0; j < 8; ++j) acc[i][j] = 0.f;

    // ---- prologue: load K-tile 0 into buffer 0 ----
#pragma unroll
    for (int i = 0; i < 2; ++i) {
        int l  = tid + i * 256;                  // 0..511
        int m  = l >> 2;                         // 0..127
        int kk = (l & 3) * 4;                    // 0,4,8,12
        float4 v = *(const float4*)&X[(size_t)(m0 + m) * KDIM + kk];
        Xs[0][kk + 0][m] = v.x; Xs[0][kk + 1][m] = v.y;
        Xs[0][kk + 2][m] = v.z; Xs[0][kk + 3][m] = v.w;
    }
#pragma unroll
    for (int i = 0; i < 2; ++i) {
        int l  = tid + i * 256;
        int kk = l >> 5;                         // 0..15
        int nn = (l & 31) * 4;                   // 0..124
        *(float4*)&Ws[0][kk][nn] = *(const float4*)&W[(size_t)kk * NDIM + n0 + nn];
    }
    __syncthreads();

    const int NKT = KDIM / 16;                   // 128
    for (int kt = 0; kt < NKT; ++kt) {
        const int cur = kt & 1, nxt = cur ^ 1;

        // prefetch next K-tile into registers
        float4 xr[2], wr[2];
        if (kt + 1 < NKT) {
            const int kb = (kt + 1) * 16;
#pragma unroll
            for (int i = 0; i < 2; ++i) {
                int l = tid + i * 256;
                int m = l >> 2, kk = (l & 3) * 4;
                xr[i] = *(const float4*)&X[(size_t)(m0 + m) * KDIM + kb + kk];
            }
#pragma unroll
            for (int i = 0; i < 2; ++i) {
                int l = tid + i * 256;
                int kk = l >> 5, nn = (l & 31) * 4;
                wr[i] = *(const float4*)&W[(size_t)(kb + kk) * NDIM + n0 + nn];
            }
        }

        // compute on current buffer
#pragma unroll
        for (int k = 0; k < 16; ++k) {
            float a[8], b[8];
            *(float4*)&a[0] = *(const float4*)&Xs[cur][k][ty * 4];
            *(float4*)&a[4] = *(const float4*)&Xs[cur][k][64 + ty * 4];
            *(float4*)&b[0] = *(const float4*)&Ws[cur][k][tx * 4];
            *(float4*)&b[4] = *(const float4*)&Ws[cur][k][64 + tx * 4];
#pragma unroll
            for (int i = 0; i < 8; ++i)
#pragma unroll
                for (int j = 0; j < 8; ++j)
                    acc[i][j] = fmaf(a[i], b[j], acc[i][j]);
        }

        // store prefetched tile into the other buffer
        if (kt + 1 < NKT) {
#pragma unroll
            for (int i = 0; i < 2; ++i) {
                int l = tid + i * 256;
                int m = l >> 2, kk = (l & 3) * 4;
                Xs[nxt][kk + 0][m] = xr[i].x; Xs[nxt][kk + 1][m] = xr[i].y;
                Xs[nxt][kk + 2][m] = xr[i].z; Xs[nxt][kk + 3][m] = xr[i].w;
                int kw = l >> 5, nn = (l & 31) * 4;
                *(float4*)&Ws[nxt][kw][nn] = wr[i];
            }
            __syncthreads();
        }
    }

    // ---- epilogue: RoPE (cols < 64) + ReLU + bias + tanh, store to g_H ----
    const int c0 = n0 + tx * 4;            // columns chunk 0
    const int c1 = n0 + 64 + tx * 4;       // columns chunk 1

    if (n0 == 0) {
        // chunk-0 columns are tx*4 .. tx*4+3, all < 64 -> RoPE applies
#pragma unroll
        for (int j = 0; j < 4; j += 2) {
            const int c = tx * 4 + j;                       // even channel of pair
            const float invf = powf(10000.0f, -(float)(c >> 1) * (1.0f / 32.0f));
#pragma unroll
            for (int i = 0; i < 8; ++i) {
                int row = m0 + ((i < 4) ? (ty * 4 + i) : (64 + ty * 4 + i - 4));
                int t = row & (TLEN - 1);
                float s, co;
                sincosf((float)t * invf, &s, &co);
                float e = acc[i][j], o = acc[i][j + 1];
                acc[i][j]     = fmaf(e, co, -o * s);        // e*cos - o*sin
                acc[i][j + 1] = fmaf(o, co,  e * s);        // o*cos + e*sin
            }
        }
    }

    float b0[4], b1[4];
#pragma unroll
    for (int j = 0; j < 4; ++j) { b0[j] = hh_b[c0 + j]; b1[j] = hh_b[c1 + j]; }

#pragma unroll
    for (int i = 0; i < 8; ++i) {
        int row = m0 + ((i < 4) ? (ty * 4 + i) : (64 + ty * 4 + i - 4));
        float4 v0, v1;
        v0.x = tanhf(fmaxf(acc[i][0], 0.f) + b0[0]);
        v0.y = tanhf(fmaxf(acc[i][1], 0.f) + b0[1]);
        v0.z = tanhf(fmaxf(acc[i][2], 0.f) + b0[2]);
        v0.w = tanhf(fmaxf(acc[i][3], 0.f) + b0[3]);
        v1.x = tanhf(fmaxf(acc[i][4], 0.f) + b1[0]);
        v1.y = tanhf(fmaxf(acc[i][5], 0.f) + b1[1]);
        v1.z = tanhf(fmaxf(acc[i][6], 0.f) + b1[2]);
        v1.w = tanhf(fmaxf(acc[i][7], 0.f) + b1[3]);
        *(float4*)&g_H[(size_t)row * NDIM + c0] = v0;
        *(float4*)&g_H[(size_t)row * NDIM + c1] = v1;
    }
}

// ---------------------------------------------------------------------------
// Kernel 2: GroupNorm over 64-channel groups + transposed write.
// CTA = one group (64 ch) x 128 rows. out[b, c*T + t] = gn[b, t, c].
// ---------------------------------------------------------------------------
__global__ __launch_bounds__(256)
void gn_transpose(const float* __restrict__ gw, const float* __restrict__ gb,
                  float* __restrict__ out)
{
    __shared__ float tile[128][65];
    __shared__ float smu[128], srs[128];

    const int g   = blockIdx.x;          // group 0..31
    const int r0  = blockIdx.y * 128;    // row block
    const int tid = threadIdx.x;

    // load 128 x 64 tile (coalesced: 16 threads cover one row)
    {
        const int c4 = (tid & 15) * 4;
        const int rb = tid >> 4;
#pragma unroll
        for (int it = 0; it < 8; ++it) {
            int r = rb + it * 16;
            float4 v = *(const float4*)&g_H[(size_t)(r0 + r) * NDIM + g * 64 + c4];
            tile[r][c4 + 0] = v.x; tile[r][c4 + 1] = v.y;
            tile[r][c4 + 2] = v.z; tile[r][c4 + 3] = v.w;
        }
    }
    __syncthreads();

    // per-row mean / var (two-pass, 1 thread per row)
    if (tid < 128) {
        float s = 0.f;
#pragma unroll
        for (int c = 0; c < 64; ++c) s += tile[tid][c];
        float mu = s * (1.f / 64.f);
        float ss = 0.f;
#pragma unroll
        for (int c = 0; c < 64; ++c) { float d = tile[tid][c] - mu; ss = fmaf(d, d, ss); }
        smu[tid] = mu;
        srs[tid] = rsqrtf(ss * (1.f / 64.f) + 1e-5f);
    }
    __syncthreads();

    // normalize + transposed write: for each channel, 128 consecutive t's
    const int t  = tid & 127;
    const int ch = tid >> 7;             // 0 or 1 (two channels per iteration)
    const int b  = r0 >> 12;             // r0 / 4096
    const float mu = smu[t], rs = srs[t];
    const size_t obase = (size_t)b * ((size_t)TLEN * NDIM)
                       + (size_t)(g * 64) * TLEN
                       + (size_t)(r0 & (TLEN - 1)) + t;
#pragma unroll
    for (int it = 0; it < 32; ++it) {
        int c = it * 2 + ch;
        float val = (tile[t][c] - mu) * rs * gw[g * 64 + c] + gb[g * 64 + c];
        out[obase + (size_t)c * TLEN] = val;
    }
}

// second output of the tuple: S_n passthrough
__global__ void copy_sn(const float* __restrict__ s, float* __restrict__ o, int n)
{
    int i = blockIdx.x * 256 + threadIdx.x;
    if (i < n) o[i] = s[i];
}

// ---------------------------------------------------------------------------
extern "C" void kernel_launch(void* const* d_in, const int* in_sizes, int n_in,
                              void* d_out, int out_size)
{
    const float* X    = (const float*)d_in[0];
    const float* S_n  = (const float*)d_in[1];
    const float* W_Q  = (const float*)d_in[2];
    const float* hhb  = (const float*)d_in[3];
    const float* gw   = (const float*)d_in[4];
    const float* gb   = (const float*)d_in[5];
    float* out = (float*)d_out;

    dim3 gg(NDIM / 128, MROWS / 128);       // (16, 64)
    gemm_fused<<<gg, 256>>>(X, W_Q, hhb);

    dim3 gn(32, MROWS / 128);               // (groups, row-blocks) = (32, 64)
    gn_transpose<<<gn, 256>>>(gw, gb, out);

    const long long OUT_ELEMS = (long long)2 * TLEN * NDIM;   // 16,777,216
    if ((long long)out_size > OUT_ELEMS) {
        int n = (int)((long long)out_size - OUT_ELEMS);
        copy_sn<<<(n + 255) / 256, 256>>>(S_n, out + OUT_ELEMS, n);
    }
}

// round 3
// speedup vs baseline: 2.1432x; 2.1432x over previous
#include <cuda_runtime.h>
#include <cuda_bf16.h>
#include <stdint.h>
#include <math.h>

#define MROWS 8192
#define KDIM  2048
#define K3    6144            // 3 * KDIM (bf16-split concatenated K)
#define NDIM  2048
#define TLEN  4096

// bf16-split operands (static device scratch)
__device__ __nv_bfloat16 g_A[(size_t)MROWS * K3];   // [m][k']  96 MB
__device__ __nv_bfloat16 g_B[(size_t)NDIM  * K3];   // [n][k']  24 MB

// ---------------------------------------------------------------------------
// helpers
// ---------------------------------------------------------------------------
__device__ __forceinline__ uint32_t smem_u32(const void* p) {
    uint32_t a;
    asm("{ .reg .u64 t; cvta.to.shared.u64 t, %1; cvt.u32.u64 %0, t; }" : "=r"(a) : "l"(p));
    return a;
}
__device__ __forceinline__ void cp16(uint32_t dst, const void* src) {
    asm volatile("cp.async.cg.shared.global [%0], [%1], 16;" :: "r"(dst), "l"(src));
}
#define CP_COMMIT() asm volatile("cp.async.commit_group;" ::: "memory")
#define CP_WAIT1()  asm volatile("cp.async.wait_group 1;" ::: "memory")
#define CP_WAIT0()  asm volatile("cp.async.wait_group 0;" ::: "memory")

__device__ __forceinline__ void ldsm_x4(uint32_t a, uint32_t& r0, uint32_t& r1,
                                        uint32_t& r2, uint32_t& r3) {
    asm volatile("ldmatrix.sync.aligned.m8n8.x4.shared.b16 {%0,%1,%2,%3}, [%4];"
                 : "=r"(r0), "=r"(r1), "=r"(r2), "=r"(r3) : "r"(a));
}
__device__ __forceinline__ void mma_bf16(float* d, const uint32_t* a, const uint32_t* b) {
    asm volatile(
        "mma.sync.aligned.m16n8k16.row.col.f32.bf16.bf16.f32 "
        "{%0,%1,%2,%3}, {%4,%5,%6,%7}, {%8,%9}, {%0,%1,%2,%3};"
        : "+f"(d[0]), "+f"(d[1]), "+f"(d[2]), "+f"(d[3])
        : "r"(a[0]), "r"(a[1]), "r"(a[2]), "r"(a[3]), "r"(b[0]), "r"(b[1]));
}

// ---------------------------------------------------------------------------
// Pre-pass 1: X fp32 -> g_A bf16 split  [hi | lo | hi]
// ---------------------------------------------------------------------------
struct alignas(8) bf4 { __nv_bfloat16 a, b, c, d; };

__global__ __launch_bounds__(256)
void convert_X(const float* __restrict__ X)
{
    int idx = blockIdx.x * 256 + threadIdx.x;        // MROWS*KDIM/4 threads
    int m  = idx >> 9;
    int k4 = (idx & 511) * 4;
    float4 v = *(const float4*)(X + (size_t)m * KDIM + k4);
    bf4 hi, lo;
    hi.a = __float2bfloat16_rn(v.x); lo.a = __float2bfloat16_rn(v.x - __bfloat162float(hi.a));
    hi.b = __float2bfloat16_rn(v.y); lo.b = __float2bfloat16_rn(v.y - __bfloat162float(hi.b));
    hi.c = __float2bfloat16_rn(v.z); lo.c = __float2bfloat16_rn(v.z - __bfloat162float(hi.c));
    hi.d = __float2bfloat16_rn(v.w); lo.d = __float2bfloat16_rn(v.w - __bfloat162float(hi.d));
    __nv_bfloat16* r = g_A + (size_t)m * K3 + k4;
    *(bf4*)(r)          = hi;     // seg0: Ah
    *(bf4*)(r + KDIM)   = lo;     // seg1: Al
    *(bf4*)(r + 2*KDIM) = hi;     // seg2: Ah
}

// ---------------------------------------------------------------------------
// Pre-pass 2: W fp32 [k][n] -> g_B bf16 split transposed: [n][ Wh | Wh | Wl ]
// ---------------------------------------------------------------------------
__global__ __launch_bounds__(256)
void convert_W(const float* __restrict__ W)
{
    __shared__ float tile[32][33];
    const int k0 = blockIdx.y * 32, n0 = blockIdx.x * 32;
    const int tx = threadIdx.x & 31, ty = threadIdx.x >> 5;   // ty 0..7
#pragma unroll
    for (int r = 0; r < 4; ++r)
        tile[ty + r * 8][tx] = W[(size_t)(k0 + ty + r * 8) * NDIM + n0 + tx];
    __syncthreads();
#pragma unroll
    for (int r = 0; r < 4; ++r) {
        int n = n0 + ty + r * 8;
        float v = tile[tx][ty + r * 8];
        __nv_bfloat16 hi = __float2bfloat16_rn(v);
        __nv_bfloat16 lo = __float2bfloat16_rn(v - __bfloat162float(hi));
        __nv_bfloat16* row = g_B + (size_t)n * K3;
        row[k0 + tx]            = hi;    // pairs with Ah
        row[KDIM + k0 + tx]     = hi;    // pairs with Al
        row[2 * KDIM + k0 + tx] = lo;    // pairs with Ah
    }
}

// ---------------------------------------------------------------------------
// Main GEMM: 128x128 tile/CTA, warp-mma m16n8k16 bf16, 3-stage cp.async.
// Fused epilogue: RoPE + ReLU + bias + tanh + GroupNorm + transposed write.
// ---------------------------------------------------------------------------
#define KCH      32
#define NIT      (K3 / KCH)          // 192
#define RSTRIDE  80                  // bytes per smem row (32 bf16 data + pad)
#define STG      20480               // A(10240) + B(10240) per stage
#define AOFFS(s) ((s) * STG)
#define BOFFS(s) ((s) * STG + 10240)
#define EPST     132                 // epilogue row stride (floats)
#define DSMEM    70656               // max(3*STG=61440, ep 67584 + stats 2048)

__global__ __launch_bounds__(256, 2)
void gemm_mma(const float* __restrict__ hh_b, const float* __restrict__ gw,
              const float* __restrict__ gb, float* __restrict__ out)
{
    extern __shared__ char smem[];
    const uint32_t sb = smem_u32(smem);
    const int tid  = threadIdx.x;
    const int wid  = tid >> 5, lane = tid & 31;
    const int wm   = wid >> 2, wn = wid & 3;      // warp grid 2(m) x 4(n)
    const int m0   = blockIdx.y * 128;
    const int n0   = blockIdx.x * 128;

    const __nv_bfloat16* Ap = g_A + (size_t)m0 * K3;
    const __nv_bfloat16* Bp = g_B + (size_t)n0 * K3;

    // per-thread loader coords: 2 chunks of 16B each for A and B
    const int lr = tid >> 2;            // row 0..63  (x2 with +64)
    const int lc = tid & 3;             // 16B chunk in row

    auto load_stage = [&](int it, int s) {
        const int kc = it * KCH;
#pragma unroll
        for (int u = 0; u < 2; ++u) {
            int r = lr + u * 64;
            cp16(sb + AOFFS(s) + r * RSTRIDE + lc * 16,
                 Ap + (size_t)r * K3 + kc + lc * 8);
            cp16(sb + BOFFS(s) + r * RSTRIDE + lc * 16,
                 Bp + (size_t)r * K3 + kc + lc * 8);
        }
        CP_COMMIT();
    };

    float acc[4][4][4];
#pragma unroll
    for (int i = 0; i < 4; ++i)
#pragma unroll
        for (int j = 0; j < 4; ++j)
#pragma unroll
            for (int e = 0; e < 4; ++e) acc[i][j][e] = 0.f;

    load_stage(0, 0);
    load_stage(1, 1);

    // ldmatrix lane addressing (constant per thread)
    const uint32_t a_row = (uint32_t)(wm * 64 + (lane & 15));
    const uint32_t a_k16 = (uint32_t)((lane >> 4) * 16);
    const uint32_t b_row = (uint32_t)(wn * 32 + ((lane >> 4) << 3) + (lane & 7));
    const uint32_t b_k16 = (uint32_t)(((lane >> 3) & 1) * 16);

    for (int it = 0; it < NIT; ++it) {
        const int s = it % 3;
        CP_WAIT1();
        __syncthreads();
        if (it + 2 < NIT) load_stage(it + 2, (it + 2) % 3);

        const uint32_t As = sb + AOFFS(s);
        const uint32_t Bs = sb + BOFFS(s);
#pragma unroll
        for (int kk = 0; kk < 2; ++kk) {
            uint32_t af[4][4], bf[4][2];
#pragma unroll
            for (int i = 0; i < 4; ++i)
                ldsm_x4(As + (a_row + i * 16) * RSTRIDE + kk * 32 + a_k16,
                        af[i][0], af[i][1], af[i][2], af[i][3]);
#pragma unroll
            for (int jj = 0; jj < 2; ++jj) {
                uint32_t r0, r1, r2, r3;
                ldsm_x4(Bs + (b_row + jj * 16) * RSTRIDE + kk * 32 + b_k16,
                        r0, r1, r2, r3);
                bf[jj * 2][0] = r0; bf[jj * 2][1] = r1;
                bf[jj * 2 + 1][0] = r2; bf[jj * 2 + 1][1] = r3;
            }
#pragma unroll
            for (int i = 0; i < 4; ++i)
#pragma unroll
                for (int j = 0; j < 4; ++j)
                    mma_bf16(acc[i][j], af[i], bf[j]);
        }
        __syncthreads();
    }
    CP_WAIT0();
    __syncthreads();   // mainloop buffers dead; smem becomes epilogue buffer

    // ---------------- fused epilogue ----------------
    float* ep = (float*)smem;                     // [128 n][EPST m]
    float* mus = (float*)(smem + 128 * EPST * 4); // [2][128]
    float* rss = mus + 256;

    const int bI = m0 >> 12;                      // batch (4096-row aligned tiles)
    const int t0 = m0 & (TLEN - 1);
    const int qr = lane >> 2;                     // row-in-8 of fragment
    const int qc = (lane & 3) * 2;                // col pair base

    // RoPE (channels < 64) + ReLU + bias + tanh, store transposed into ep[n][m]
#pragma unroll
    for (int i = 0; i < 4; ++i) {
#pragma unroll
        for (int j = 0; j < 4; ++j) {
            const int colg = n0 + wn * 32 + j * 8 + qc;      // global even channel
            const int coll = wn * 32 + j * 8 + qc;           // tile-local
            float c0 = acc[i][j][0], c1 = acc[i][j][1];
            float c2 = acc[i][j][2], c3 = acc[i][j][3];
            const int r0 = wm * 64 + i * 16 + qr;            // tile-local rows
            const int r1 = r0 + 8;
            if (colg < 64) {
                const float inv = powf(10000.0f, -(float)(colg >> 1) * (1.0f / 32.0f));
                float sn, cs;
                sincosf((float)((m0 + r0) & (TLEN - 1)) * inv, &sn, &cs);
                float e = c0, o = c1;
                c0 = e * cs - o * sn;  c1 = o * cs + e * sn;
                sincosf((float)((m0 + r1) & (TLEN - 1)) * inv, &sn, &cs);
                e = c2; o = c3;
                c2 = e * cs - o * sn;  c3 = o * cs + e * sn;
            }
            const float be = __ldg(hh_b + colg), bo = __ldg(hh_b + colg + 1);
            ep[coll * EPST + r0]       = tanhf(fmaxf(c0, 0.f) + be);
            ep[(coll + 1) * EPST + r0] = tanhf(fmaxf(c1, 0.f) + bo);
            ep[coll * EPST + r1]       = tanhf(fmaxf(c2, 0.f) + be);
            ep[(coll + 1) * EPST + r1] = tanhf(fmaxf(c3, 0.f) + bo);
        }
    }
    __syncthreads();

    // per-row GroupNorm stats over each 64-channel group in this tile
    {
        const int m = tid & 127, g = tid >> 7;    // 256 threads = 128 rows x 2 groups
        float s = 0.f;
#pragma unroll
        for (int c = 0; c < 64; ++c) s += ep[(g * 64 + c) * EPST + m];
        float mu = s * (1.f / 64.f);
        float ss = 0.f;
#pragma unroll
        for (int c = 0; c < 64; ++c) {
            float d = ep[(g * 64 + c) * EPST + m] - mu;
            ss = fmaf(d, d, ss);
        }
        mus[g * 128 + m] = mu;
        rss[g * 128 + m] = rsqrtf(ss * (1.f / 64.f) + 1e-5f);
    }
    __syncthreads();

    // normalize + transposed coalesced write: out[b, (n0+c)*T + t0 + m]
#pragma unroll
    for (int u = 0; u < 16; ++u) {
        int idx = tid + u * 256;                  // 0..4095 float4 slots
        int cn = idx >> 5, q = idx & 31;
        int g = cn >> 6;
        float w = __ldg(gw + n0 + cn), b = __ldg(gb + n0 + cn);
        float4 v = *(float4*)&ep[cn * EPST + q * 4];
        v.x = (v.x - mus[g * 128 + q * 4 + 0]) * rss[g * 128 + q * 4 + 0] * w + b;
        v.y = (v.y - mus[g * 128 + q * 4 + 1]) * rss[g * 128 + q * 4 + 1] * w + b;
        v.z = (v.z - mus[g * 128 + q * 4 + 2]) * rss[g * 128 + q * 4 + 2] * w + b;
        v.w = (v.w - mus[g * 128 + q * 4 + 3]) * rss[g * 128 + q * 4 + 3] * w + b;
        *(float4*)&out[(size_t)bI * TLEN * NDIM + (size_t)(n0 + cn) * TLEN
                       + t0 + q * 4] = v;
    }
}

// second output of the tuple: S_n passthrough
__global__ void copy_sn(const float* __restrict__ s, float* __restrict__ o, int n)
{
    int i = blockIdx.x * 256 + threadIdx.x;
    if (i < n) o[i] = s[i];
}

// ---------------------------------------------------------------------------
extern "C" void kernel_launch(void* const* d_in, const int* in_sizes, int n_in,
                              void* d_out, int out_size)
{
    const float* X   = (const float*)d_in[0];
    const float* S_n = (const float*)d_in[1];
    const float* W_Q = (const float*)d_in[2];
    const float* hhb = (const float*)d_in[3];
    const float* gw  = (const float*)d_in[4];
    const float* gb  = (const float*)d_in[5];
    float* out = (float*)d_out;

    static bool attr_done = false;
    if (!attr_done) {
        cudaFuncSetAttribute(gemm_mma, cudaFuncAttributeMaxDynamicSharedMemorySize,
                             DSMEM);
        attr_done = true;
    }

    convert_X<<<(MROWS * KDIM / 4) / 256, 256>>>(X);
    convert_W<<<dim3(NDIM / 32, KDIM / 32), 256>>>(W_Q);

    dim3 gg(NDIM / 128, MROWS / 128);    // (16, 64)
    gemm_mma<<<gg, 256, DSMEM>>>(hhb, gw, gb, out);

    const long long OUT_ELEMS = (long long)2 * TLEN * NDIM;
    if ((long long)out_size > OUT_ELEMS) {
        int n = (int)((long long)out_size - OUT_ELEMS);
        copy_sn<<<(n + 255) / 256, 256>>>(S_n, out + OUT_ELEMS, n);
    }
}

// round 4
// speedup vs baseline: 3.9779x; 1.8561x over previous
#include <cuda_runtime.h>
#include <cuda_fp16.h>
#include <stdint.h>
#include <math.h>

#define MROWS 8192
#define KDIM  2048
#define K4    4096            // 2 * KDIM (fp16-split concatenated K)
#define NDIM  2048
#define TLEN  4096
#define WSCALE 2048.0f
#define INVW   (1.0f / 2048.0f)

// fp16-split operands (static device scratch)
__device__ __half g_A[(size_t)MROWS * K4];   // [m][ Xh | Xl ]   64 MB
__device__ __half g_B[(size_t)NDIM * KDIM];  // [n][ Wh*2048 ]    8 MB

// ---------------------------------------------------------------------------
// helpers
// ---------------------------------------------------------------------------
__device__ __forceinline__ uint32_t smem_u32(const void* p) {
    uint32_t a;
    asm("{ .reg .u64 t; cvta.to.shared.u64 t, %1; cvt.u32.u64 %0, t; }" : "=r"(a) : "l"(p));
    return a;
}
__device__ __forceinline__ void cp16(uint32_t dst, const void* src) {
    asm volatile("cp.async.cg.shared.global [%0], [%1], 16;" :: "r"(dst), "l"(src));
}
#define CP_COMMIT() asm volatile("cp.async.commit_group;" ::: "memory")
#define CP_WAIT1()  asm volatile("cp.async.wait_group 1;" ::: "memory")
#define CP_WAIT0()  asm volatile("cp.async.wait_group 0;" ::: "memory")

__device__ __forceinline__ void ldsm_x4(uint32_t a, uint32_t& r0, uint32_t& r1,
                                        uint32_t& r2, uint32_t& r3) {
    asm volatile("ldmatrix.sync.aligned.m8n8.x4.shared.b16 {%0,%1,%2,%3}, [%4];"
                 : "=r"(r0), "=r"(r1), "=r"(r2), "=r"(r3) : "r"(a));
}
__device__ __forceinline__ void mma_f16(float* d, const uint32_t* a, const uint32_t* b) {
    asm volatile(
        "mma.sync.aligned.m16n8k16.row.col.f32.f16.f16.f32 "
        "{%0,%1,%2,%3}, {%4,%5,%6,%7}, {%8,%9}, {%0,%1,%2,%3};"
        : "+f"(d[0]), "+f"(d[1]), "+f"(d[2]), "+f"(d[3])
        : "r"(a[0]), "r"(a[1]), "r"(a[2]), "r"(a[3]), "r"(b[0]), "r"(b[1]));
}

// ---------------------------------------------------------------------------
// Pre-pass 1: X fp32 -> g_A fp16 split [hi | lo]; also copies S_n tail.
// ---------------------------------------------------------------------------
struct alignas(8) h4 { __half a, b, c, d; };

__global__ __launch_bounds__(256)
void convert_X(const float* __restrict__ X, const float* __restrict__ S_n,
               float* __restrict__ tail, int ntail)
{
    int idx = blockIdx.x * 256 + threadIdx.x;        // MROWS*KDIM/4 threads
    int m  = idx >> 9;
    int k4 = (idx & 511) * 4;
    float4 v = *(const float4*)(X + (size_t)m * KDIM + k4);
    h4 hi, lo;
    hi.a = __float2half_rn(v.x); lo.a = __float2half_rn(v.x - __half2float(hi.a));
    hi.b = __float2half_rn(v.y); lo.b = __float2half_rn(v.y - __half2float(hi.b));
    hi.c = __float2half_rn(v.z); lo.c = __float2half_rn(v.z - __half2float(hi.c));
    hi.d = __float2half_rn(v.w); lo.d = __float2half_rn(v.w - __half2float(hi.d));
    __half* r = g_A + (size_t)m * K4 + k4;
    *(h4*)(r)        = hi;
    *(h4*)(r + KDIM) = lo;
    if (idx < ntail) tail[idx] = S_n[idx];           // S_n passthrough
}

// ---------------------------------------------------------------------------
// Pre-pass 2: W fp32 [k][n] -> g_B fp16 transposed, scaled by 2048: [n][k]
// ---------------------------------------------------------------------------
__global__ __launch_bounds__(256)
void convert_W(const float* __restrict__ W)
{
    __shared__ float tile[32][33];
    const int k0 = blockIdx.y * 32, n0 = blockIdx.x * 32;
    const int tx = threadIdx.x & 31, ty = threadIdx.x >> 5;
#pragma unroll
    for (int r = 0; r < 4; ++r)
        tile[ty + r * 8][tx] = W[(size_t)(k0 + ty + r * 8) * NDIM + n0 + tx];
    __syncthreads();
#pragma unroll
    for (int r = 0; r < 4; ++r) {
        int n = n0 + ty + r * 8;
        g_B[(size_t)n * KDIM + k0 + tx] = __float2half_rn(tile[tx][ty + r * 8] * WSCALE);
    }
}

// ---------------------------------------------------------------------------
// Main GEMM: 128x128 tile/CTA, m16n8k16 fp16, KCH=64, 3-stage cp.async,
// SW128-swizzled SMEM. Fused RoPE/ReLU/bias/tanh/GroupNorm/transpose epilogue.
// ---------------------------------------------------------------------------
#define KCH      64
#define NIT      (K4 / KCH)          // 64
#define STG      32768               // A 16KB + B 16KB per stage
#define AOFFS(s) ((s) * STG)
#define BOFFS(s) ((s) * STG + 16384)
#define EPST     132
#define DSMEM    98304               // 3 stages; epilogue (69,632B) reuses it

__global__ __launch_bounds__(256, 2)
void gemm_mma(const float* __restrict__ hh_b, const float* __restrict__ gw,
              const float* __restrict__ gb, float* __restrict__ out)
{
    extern __shared__ char smem[];
    const uint32_t sb = smem_u32(smem);
    const int tid  = threadIdx.x;
    const int wid  = tid >> 5, lane = tid & 31;
    const int wm   = wid >> 2, wn = wid & 3;      // warp grid 2(m) x 4(n)
    const int m0   = blockIdx.y * 128;
    const int n0   = blockIdx.x * 128;

    const __half* Ap = g_A + (size_t)m0 * K4;
    const __half* Bp = g_B + (size_t)n0 * KDIM;

    auto load_stage = [&](int it, int s) {
        const int kc  = it * KCH;
        const int kcb = kc & (KDIM - 1);           // B has one 2048-wide copy
#pragma unroll
        for (int u = 0; u < 4; ++u) {
            int ci = tid + u * 256;                // 0..1023
            int r = ci >> 3, c = ci & 7;
            uint32_t dof = (uint32_t)(r * 128 + ((c ^ (r & 7)) << 4));
            cp16(sb + AOFFS(s) + dof, Ap + (size_t)r * K4 + kc + c * 8);
            cp16(sb + BOFFS(s) + dof, Bp + (size_t)r * KDIM + kcb + c * 8);
        }
        CP_COMMIT();
    };

    float acc[4][4][4];
#pragma unroll
    for (int i = 0; i < 4; ++i)
#pragma unroll
        for (int j = 0; j < 4; ++j)
#pragma unroll
            for (int e = 0; e < 4; ++e) acc[i][j][e] = 0.f;

    load_stage(0, 0);
    load_stage(1, 1);

    // ldmatrix lane coords (SW128: chunk-col XOR (row&7))
    const int a_row = wm * 64 + (lane & 15);
    const int a_cb  = lane >> 4;                      // 0/1: 16B chunk within k16
    const int b_row = wn * 32 + ((lane >> 4) << 3) + (lane & 7);
    const int b_cb  = (lane >> 3) & 1;

    for (int it = 0; it < NIT; ++it) {
        const int s = it % 3;
        if (it + 2 < NIT) { CP_WAIT1(); } else { CP_WAIT0(); }
        __syncthreads();
        if (it + 2 < NIT) load_stage(it + 2, (it + 2) % 3);

        const uint32_t As = sb + AOFFS(s);
        const uint32_t Bs = sb + BOFFS(s);
#pragma unroll
        for (int kk = 0; kk < 4; ++kk) {
            uint32_t af[4][4], bf[4][2];
#pragma unroll
            for (int i = 0; i < 4; ++i) {
                int r = a_row + i * 16;
                int c = (kk * 2 + a_cb) ^ (r & 7);
                ldsm_x4(As + r * 128 + c * 16, af[i][0], af[i][1], af[i][2], af[i][3]);
            }
#pragma unroll
            for (int jj = 0; jj < 2; ++jj) {
                int r = b_row + jj * 16;
                int c = (kk * 2 + b_cb) ^ (r & 7);
                uint32_t r0, r1, r2, r3;
                ldsm_x4(Bs + r * 128 + c * 16, r0, r1, r2, r3);
                bf[jj * 2][0] = r0;     bf[jj * 2][1] = r1;
                bf[jj * 2 + 1][0] = r2; bf[jj * 2 + 1][1] = r3;
            }
#pragma unroll
            for (int i = 0; i < 4; ++i)
#pragma unroll
                for (int j = 0; j < 4; ++j)
                    mma_f16(acc[i][j], af[i], bf[j]);
        }
        __syncthreads();
    }

    // ---------------- fused epilogue (scale by 1/2048 for W prescale) -------
    float* ep  = (float*)smem;                     // [128 n][EPST m]
    float* mus = (float*)(smem + 128 * EPST * 4);  // [2][128]
    float* rss = mus + 256;

    const int bI = m0 >> 12;
    const int t0 = m0 & (TLEN - 1);
    const int qr = lane >> 2;
    const int qc = (lane & 3) * 2;

#pragma unroll
    for (int i = 0; i < 4; ++i) {
#pragma unroll
        for (int j = 0; j < 4; ++j) {
            const int colg = n0 + wn * 32 + j * 8 + qc;
            const int coll = wn * 32 + j * 8 + qc;
            float c0 = acc[i][j][0] * INVW, c1 = acc[i][j][1] * INVW;
            float c2 = acc[i][j][2] * INVW, c3 = acc[i][j][3] * INVW;
            const int r0 = wm * 64 + i * 16 + qr;
            const int r1 = r0 + 8;
            if (colg < 64) {
                const float inv = powf(10000.0f, -(float)(colg >> 1) * (1.0f / 32.0f));
                float sn, cs;
                sincosf((float)((m0 + r0) & (TLEN - 1)) * inv, &sn, &cs);
                float e = c0, o = c1;
                c0 = e * cs - o * sn;  c1 = o * cs + e * sn;
                sincosf((float)((m0 + r1) & (TLEN - 1)) * inv, &sn, &cs);
                e = c2; o = c3;
                c2 = e * cs - o * sn;  c3 = o * cs + e * sn;
            }
            const float be = __ldg(hh_b + colg), bo = __ldg(hh_b + colg + 1);
            ep[coll * EPST + r0]       = tanhf(fmaxf(c0, 0.f) + be);
            ep[(coll + 1) * EPST + r0] = tanhf(fmaxf(c1, 0.f) + bo);
            ep[coll * EPST + r1]       = tanhf(fmaxf(c2, 0.f) + be);
            ep[(coll + 1) * EPST + r1] = tanhf(fmaxf(c3, 0.f) + bo);
        }
    }
    __syncthreads();

    {   // per-row GroupNorm stats over each 64-channel group
        const int m = tid & 127, g = tid >> 7;
        float s = 0.f;
#pragma unroll
        for (int c = 0; c < 64; ++c) s += ep[(g * 64 + c) * EPST + m];
        float mu = s * (1.f / 64.f);
        float ss = 0.f;
#pragma unroll
        for (int c = 0; c < 64; ++c) {
            float d = ep[(g * 64 + c) * EPST + m] - mu;
            ss = fmaf(d, d, ss);
        }
        mus[g * 128 + m] = mu;
        rss[g * 128 + m] = rsqrtf(ss * (1.f / 64.f) + 1e-5f);
    }
    __syncthreads();

    // normalize + transposed coalesced write
#pragma unroll
    for (int u = 0; u < 16; ++u) {
        int idx = tid + u * 256;
        int cn = idx >> 5, q = idx & 31;
        int g = cn >> 6;
        float w = __ldg(gw + n0 + cn), b = __ldg(gb + n0 + cn);
        float4 v = *(float4*)&ep[cn * EPST + q * 4];
        v.x = (v.x - mus[g * 128 + q * 4 + 0]) * rss[g * 128 + q * 4 + 0] * w + b;
        v.y = (v.y - mus[g * 128 + q * 4 + 1]) * rss[g * 128 + q * 4 + 1] * w + b;
        v.z = (v.z - mus[g * 128 + q * 4 + 2]) * rss[g * 128 + q * 4 + 2] * w + b;
        v.w = (v.w - mus[g * 128 + q * 4 + 3]) * rss[g * 128 + q * 4 + 3] * w + b;
        *(float4*)&out[(size_t)bI * TLEN * NDIM + (size_t)(n0 + cn) * TLEN
                       + t0 + q * 4] = v;
    }
}

// ---------------------------------------------------------------------------
extern "C" void kernel_launch(void* const* d_in, const int* in_sizes, int n_in,
                              void* d_out, int out_size)
{
    const float* X   = (const float*)d_in[0];
    const float* S_n = (const float*)d_in[1];
    const float* W_Q = (const float*)d_in[2];
    const float* hhb = (const float*)d_in[3];
    const float* gw  = (const float*)d_in[4];
    const float* gb  = (const float*)d_in[5];
    float* out = (float*)d_out;

    static bool attr_done = false;
    if (!attr_done) {
        cudaFuncSetAttribute(gemm_mma, cudaFuncAttributeMaxDynamicSharedMemorySize,
                             DSMEM);
        attr_done = true;
    }

    const long long OUT_ELEMS = (long long)2 * TLEN * NDIM;
    int ntail = (int)((long long)out_size - OUT_ELEMS);
    if (ntail < 0) ntail = 0;

    convert_X<<<(MROWS * KDIM / 4) / 256, 256>>>(X, S_n, out + OUT_ELEMS, ntail);
    convert_W<<<dim3(NDIM / 32, KDIM / 32), 256>>>(W_Q);

    dim3 gg(NDIM / 128, MROWS / 128);    // (16, 64)
    gemm_mma<<<gg, 256, DSMEM>>>(hhb, gw, gb, out);
}